// round 5
// baseline (speedup 1.0000x reference)
#include <cuda_runtime.h>

// ComponentWiseSpline: rational-quadratic spline flow, forward + log|det J|.
// B=65536 rows, D=128 dims, K=8 interior bins.
// R5: 512-thread blocks (3/SM -> 75% occ ceiling, regs capped 42),
//     one row in flight + x prefetch, integer-mask bin search (IADD3 tree),
//     identity-extended 10-bin table, persistent 148x3 grid.

#define BB 65536
#define DD 128
#define KK 8
#define NBINS 10                       // identity | 8 interior | identity
#define BLOCK 512
#define TEAMS 4                        // 4-warp team per row-stream
#define GRIDB 444                      // 148 SMs * 3 blocks
#define NS (GRIDB * TEAMS)             // 1776 row streams
#define MAXR ((BB + NS - 1) / NS)      // 37

__global__ void __launch_bounds__(BLOCK, 3)
spline_kernel(const float* __restrict__ x,
              const float* __restrict__ uw,
              const float* __restrict__ uh,
              const float* __restrict__ ud,
              float* __restrict__ uout,
              float* __restrict__ ldout) {
    __shared__ float4 sTA[NBINS * DD];     // 20 KB {invW, -cw*invW, cumH, H}
    __shared__ float4 sTB[NBINS * DD];     // 20 KB {delta, d0, d1, e}
    __shared__ float  sThr[9 * DD];        // 4.5 KB
    __shared__ float  sPart[TEAMS][4][MAXR];

    const int tid   = threadIdx.x;
    const int lane  = tid & 31;
    const int warp  = tid >> 5;            // 0..15
    const int team  = warp >> 2;           // 0..3
    const int wslot = warp & 3;            // 0..3
    const int d     = (wslot << 5) + lane; // dim owned by this lane

    // ---- per-block table build: thread dd (<128) builds dim dd ----
    if (tid < DD) {
        const float BOUND = 3.0f;
        const float MINW = 1e-3f, MINH = 1e-3f, MIND = 1e-3f, EPS = 1e-6f;
        const int dd = tid;

        float w[KK], h[KK];
        float m = -1e30f;
        #pragma unroll
        for (int k = 0; k < KK; k++) { w[k] = uw[dd * KK + k]; m = fmaxf(m, w[k]); }
        float s = 0.f;
        #pragma unroll
        for (int k = 0; k < KK; k++) { w[k] = expf(w[k] - m); s += w[k]; }
        float invs = 1.0f / s;
        #pragma unroll
        for (int k = 0; k < KK; k++) w[k] = MINW + (1.0f - MINW * KK) * (w[k] * invs);

        m = -1e30f;
        #pragma unroll
        for (int k = 0; k < KK; k++) { h[k] = uh[dd * KK + k]; m = fmaxf(m, h[k]); }
        s = 0.f;
        #pragma unroll
        for (int k = 0; k < KK; k++) { h[k] = expf(h[k] - m); s += h[k]; }
        invs = 1.0f / s;
        #pragma unroll
        for (int k = 0; k < KK; k++) h[k] = MINH + (1.0f - MINH * KK) * (h[k] * invs);

        float cw[KK + 1], ch[KK + 1];
        cw[0] = -BOUND; ch[0] = -BOUND;
        float accw = 0.f, acch = 0.f;
        #pragma unroll
        for (int k = 1; k < KK; k++) {
            accw += w[k - 1]; cw[k] = fmaf(2.0f * BOUND, accw, -BOUND);
            acch += h[k - 1]; ch[k] = fmaf(2.0f * BOUND, acch, -BOUND);
        }
        cw[KK] = BOUND; ch[KK] = BOUND;

        float dv[KK + 1];
        dv[0] = 1.0f - MIND; dv[KK] = 1.0f - MIND;
        #pragma unroll
        for (int k = 1; k < KK; k++) {
            float v = ud[dd * (KK - 1) + (k - 1)];
            dv[k] = MIND + fmaxf(v, 0.0f) + log1pf(expf(-fabsf(v)));
        }

        // interior bins -> slot k+1
        #pragma unroll
        for (int k = 0; k < KK; k++) {
            float W = cw[k + 1] - cw[k];
            float H = ch[k + 1] - ch[k];
            float invW = 1.0f / W;
            float del  = H * invW;
            sTA[(k + 1) * DD + dd] = make_float4(invW, -cw[k] * invW, ch[k], H);
            sTB[(k + 1) * DD + dd] = make_float4(del, dv[k], dv[k + 1],
                                                 dv[k] + dv[k + 1] - 2.0f * del);
        }
        // identity bins 0 (x < -3) and 9 (x > 3): u = x, lad = 0.
        const float4 idA = make_float4(1.0f, 0.0f, 0.0f, 1.0f);
        const float4 idB = make_float4(1.0f, 1.0f, 1.0f, 0.0f);
        sTA[0 * DD + dd] = idA; sTB[0 * DD + dd] = idB;
        sTA[9 * DD + dd] = idA; sTB[9 * DD + dd] = idB;

        sThr[0 * DD + dd] = -3.0f;                          // enter interior
        #pragma unroll
        for (int t = 1; t < 8; t++) sThr[t * DD + dd] = cw[t] + EPS;
        sThr[8 * DD + dd] = __int_as_float(0x40400001);     // nextafter(3.0f)
    }
    __syncthreads();

    // ---- this lane's 9 thresholds into registers ----
    float thr[9];
    #pragma unroll
    for (int j = 0; j < 9; j++) thr[j] = sThr[j * DD + d];

    const int S = blockIdx.x * TEAMS + team;   // stream id, 0..NS-1
    int row = S;
    const float* px = x + (size_t)row * DD + d;
    float*       pu = uout + (size_t)row * DD + d;
    float xv = *px;                            // S < NS < BB always valid
    int ri = 0;

    while (true) {
        const int nrow = row + NS;
        const float* pn = px + (size_t)NS * DD;
        float xn;
        if (nrow < BB) xn = __ldg(pn);         // prefetch next row

        // 10-way bin select via integer masks: s = -#{j : xv >= thr[j]}
        int s = 0;
        #pragma unroll
        for (int j = 0; j < 9; j++) {
            unsigned mm;
            asm("set.ge.u32.f32 %0, %1, %2;" : "=r"(mm) : "f"(xv), "f"(thr[j]));
            s += (int)mm;                      // masks are 0 or -1
        }
        const int idx = d - (s << 7);          // k*128 + d, k = -s

        const float4 A  = sTA[idx];            // invW, -cw*invW, cumH, H
        const float4 Bv = sTB[idx];            // delta, d0, d1, e

        const float theta = fmaf(xv, A.x, A.y);
        const float omt   = 1.0f - theta;
        const float th2   = theta * theta;
        const float t1m   = theta * omt;
        const float omt2  = omt * omt;
        const float t1m2  = t1m + t1m;

        const float num    = A.w * fmaf(Bv.x, th2, Bv.y * t1m);
        const float den    = fmaf(Bv.w, t1m, Bv.x);
        const float invden = __fdividef(1.0f, den);
        const float uo     = fmaf(num, invden, A.z);

        const float inner = fmaf(Bv.z, th2, fmaf(Bv.x, t1m2, Bv.y * omt2));
        const float dnum  = (Bv.x * Bv.x) * inner;
        float la = __logf(dnum * (invden * invden));

        *pu = uo;

        #pragma unroll
        for (int off = 16; off; off >>= 1)
            la += __shfl_xor_sync(0xffffffffu, la, off);
        if (lane == 0) sPart[team][wslot][ri] = la;

        ri++;
        if (nrow >= BB) break;
        row = nrow;
        px = pn;
        pu += (size_t)NS * DD;
        xv = xn;
    }
    __syncthreads();

    // ---- combine the 4 warp partials per row, write log|det J| ----
    if (tid < TEAMS * MAXR) {
        const int tm  = tid / MAXR;
        const int rii = tid - tm * MAXR;
        const int r   = blockIdx.x * TEAMS + tm + rii * NS;
        if (r < BB)
            ldout[r] = (sPart[tm][0][rii] + sPart[tm][1][rii]) +
                       (sPart[tm][2][rii] + sPart[tm][3][rii]);
    }
}

extern "C" void kernel_launch(void* const* d_in, const int* in_sizes, int n_in,
                              void* d_out, int out_size) {
    const float* x  = (const float*)d_in[0];
    const float* uw = (const float*)d_in[1];
    const float* uh = (const float*)d_in[2];
    const float* ud = (const float*)d_in[3];
    float* out = (float*)d_out;

    spline_kernel<<<GRIDB, BLOCK>>>(x, uw, uh, ud, out, out + (size_t)BB * DD);
}

// round 6
// speedup vs baseline: 1.1231x; 1.1231x over previous
#include <cuda_runtime.h>

// ComponentWiseSpline: rational-quadratic spline flow, forward + log|det J|.
// B=65536 rows, D=128 dims, K=8 interior bins.
// R6: R4 structure (FSET+FADD search, identity-extended 10-bin table,
//     2 teams x 4 warps, 2 rows/iter) + depth-2 x prefetch + magic-number
//     bin index (FFMA+LOP3 instead of F2I+IMAD).

#define BB 65536
#define DD 128
#define KK 8
#define NBINS 10                         // identity | 8 interior | identity
#define NPAIRS (BB / 2)                  // 32768 row-pairs
#define GRIDB 592                        // 148 SMs * 4 blocks
#define NS (GRIDB * 2)                   // 1184 row-pair streams (2 teams/block)
#define MAXP ((NPAIRS + NS - 1) / NS)    // 28

__device__ __forceinline__ float fsetge(float a, float b) {
    float r;
    asm("set.ge.f32.f32 %0, %1, %2;" : "=f"(r) : "f"(a), "f"(b));
    return r;
}

__global__ void __launch_bounds__(256, 4)
spline_kernel(const float* __restrict__ x,
              const float* __restrict__ uw,
              const float* __restrict__ uh,
              const float* __restrict__ ud,
              float* __restrict__ uout,
              float* __restrict__ ldout) {
    __shared__ float4 sTA[NBINS * DD];        // 20 KB {invW, -cw*invW, cumH, H}
    __shared__ float4 sTB[NBINS * DD];        // 20 KB {delta, d0, d1, e}
    __shared__ float  sThr[9 * DD];           // 4.5 KB
    __shared__ float  sPart[2][4][MAXP][2];   // 1.75 KB

    const int tid  = threadIdx.x;
    const int lane = tid & 31;
    const int warp = tid >> 5;
    const int team = warp >> 2;      // 0..1
    const int wslot = warp & 3;      // 0..3
    const int d = (wslot << 5) + lane;

    // ---- per-block table build: thread dd (<128) builds dim dd ----
    if (tid < DD) {
        const float BOUND = 3.0f;
        const float MINW = 1e-3f, MINH = 1e-3f, MIND = 1e-3f, EPS = 1e-6f;
        const int dd = tid;

        float w[KK], h[KK];
        float m = -1e30f;
        #pragma unroll
        for (int k = 0; k < KK; k++) { w[k] = uw[dd * KK + k]; m = fmaxf(m, w[k]); }
        float s = 0.f;
        #pragma unroll
        for (int k = 0; k < KK; k++) { w[k] = expf(w[k] - m); s += w[k]; }
        float invs = 1.0f / s;
        #pragma unroll
        for (int k = 0; k < KK; k++) w[k] = MINW + (1.0f - MINW * KK) * (w[k] * invs);

        m = -1e30f;
        #pragma unroll
        for (int k = 0; k < KK; k++) { h[k] = uh[dd * KK + k]; m = fmaxf(m, h[k]); }
        s = 0.f;
        #pragma unroll
        for (int k = 0; k < KK; k++) { h[k] = expf(h[k] - m); s += h[k]; }
        invs = 1.0f / s;
        #pragma unroll
        for (int k = 0; k < KK; k++) h[k] = MINH + (1.0f - MINH * KK) * (h[k] * invs);

        float cw[KK + 1], ch[KK + 1];
        cw[0] = -BOUND; ch[0] = -BOUND;
        float accw = 0.f, acch = 0.f;
        #pragma unroll
        for (int k = 1; k < KK; k++) {
            accw += w[k - 1]; cw[k] = fmaf(2.0f * BOUND, accw, -BOUND);
            acch += h[k - 1]; ch[k] = fmaf(2.0f * BOUND, acch, -BOUND);
        }
        cw[KK] = BOUND; ch[KK] = BOUND;

        float dv[KK + 1];
        dv[0] = 1.0f - MIND; dv[KK] = 1.0f - MIND;
        #pragma unroll
        for (int k = 1; k < KK; k++) {
            float v = ud[dd * (KK - 1) + (k - 1)];
            dv[k] = MIND + fmaxf(v, 0.0f) + log1pf(expf(-fabsf(v)));
        }

        // interior bins -> slot k+1
        #pragma unroll
        for (int k = 0; k < KK; k++) {
            float W = cw[k + 1] - cw[k];
            float H = ch[k + 1] - ch[k];
            float invW = 1.0f / W;
            float del  = H * invW;
            sTA[(k + 1) * DD + dd] = make_float4(invW, -cw[k] * invW, ch[k], H);
            sTB[(k + 1) * DD + dd] = make_float4(del, dv[k], dv[k + 1],
                                                 dv[k] + dv[k + 1] - 2.0f * del);
        }
        // identity bins 0 (x < -3) and 9 (x > 3): u = x, lad = 0.
        const float4 idA = make_float4(1.0f, 0.0f, 0.0f, 1.0f);
        const float4 idB = make_float4(1.0f, 1.0f, 1.0f, 0.0f);
        sTA[0 * DD + dd] = idA; sTB[0 * DD + dd] = idB;
        sTA[9 * DD + dd] = idA; sTB[9 * DD + dd] = idB;

        sThr[0 * DD + dd] = -3.0f;
        #pragma unroll
        for (int t = 1; t < 8; t++) sThr[t * DD + dd] = cw[t] + EPS;
        sThr[8 * DD + dd] = __int_as_float(0x40400001);   // nextafter(3.0f)
    }
    __syncthreads();

    // ---- this lane's 9 thresholds into registers ----
    float thr[9];
    #pragma unroll
    for (int j = 0; j < 9; j++) thr[j] = sThr[j * DD + d];

    const int S = blockIdx.x * 2 + team;            // stream id, 0..NS-1
    const size_t STEP = (size_t)NS * 256;           // floats per stream step

    int p = S;                                      // current row-pair
    const float* px = x + (size_t)p * 256 + d;      // current x base
    float*       pu = uout + (size_t)p * 256 + d;   // current out base
    float xa = px[0];
    float xb = px[DD];
    float xa1, xb1;
    if (p + NS < NPAIRS) { xa1 = __ldg(px + STEP); xb1 = __ldg(px + STEP + DD); }
    int pi = 0;

    while (true) {
        // depth-2 prefetch
        float xa2, xb2;
        if (p + 2 * NS < NPAIRS) {
            xa2 = __ldg(px + 2 * STEP);
            xb2 = __ldg(px + 2 * STEP + DD);
        }

        float lads[2];
        float xin[2] = {xa, xb};
        #pragma unroll
        for (int e = 0; e < 2; e++) {
            const float xv = xin[e];
            // 10-way bin count as float (FSET on alu, FADD on fma)
            float s0 = fsetge(xv, thr[0]) + fsetge(xv, thr[1]);
            float s1 = fsetge(xv, thr[2]) + fsetge(xv, thr[3]);
            float s2 = fsetge(xv, thr[4]) + fsetge(xv, thr[5]);
            float s3 = fsetge(xv, thr[6]) + fsetge(xv, thr[7]);
            float kf = ((s0 + s1) + (s2 + s3)) + fsetge(xv, thr[8]);
            // magic: bits(2^23 + 128*k) low 16 bits == 128*k  (exact, k<=9)
            int kbits = __float_as_int(fmaf(kf, 128.0f, 8388608.0f));
            const int idx = (kbits & 0xFFFF) + d;

            const float4 A  = sTA[idx];   // invW, -cw*invW, cumH, H
            const float4 Bv = sTB[idx];   // delta, d0, d1, e

            const float theta = fmaf(xv, A.x, A.y);
            const float omt   = 1.0f - theta;
            const float th2   = theta * theta;
            const float t1m   = theta * omt;
            const float omt2  = omt * omt;
            const float t1m2  = t1m + t1m;

            const float num    = A.w * fmaf(Bv.x, th2, Bv.y * t1m);
            const float den    = fmaf(Bv.w, t1m, Bv.x);
            const float invden = __fdividef(1.0f, den);
            const float uo     = fmaf(num, invden, A.z);

            const float inner = fmaf(Bv.z, th2, fmaf(Bv.x, t1m2, Bv.y * omt2));
            const float dnum  = (Bv.x * Bv.x) * inner;
            lads[e] = __logf(dnum * (invden * invden));

            pu[e ? DD : 0] = uo;          // store immediately, free the reg
        }

        float la = lads[0], lb = lads[1];
        #pragma unroll
        for (int off = 16; off; off >>= 1) {
            la += __shfl_xor_sync(0xffffffffu, la, off);
            lb += __shfl_xor_sync(0xffffffffu, lb, off);
        }
        if (lane == 0) {
            sPart[team][wslot][pi][0] = la;
            sPart[team][wslot][pi][1] = lb;
        }

        pi++;
        p += NS;
        if (p >= NPAIRS) break;
        px += STEP;
        pu += STEP;
        xa = xa1; xb = xb1;
        xa1 = xa2; xb1 = xb2;
    }
    __syncthreads();

    // ---- combine 4 warp-partials per row, write log|det J| ----
    if (tid < 2 * MAXP * 2) {
        const int tm   = tid / (MAXP * 2);
        const int rem  = tid - tm * (MAXP * 2);
        const int ppi  = rem >> 1;
        const int half = rem & 1;
        const int gp   = blockIdx.x * 2 + tm + ppi * NS;
        if (gp < NPAIRS) {
            float v = sPart[tm][0][ppi][half] + sPart[tm][1][ppi][half]
                    + sPart[tm][2][ppi][half] + sPart[tm][3][ppi][half];
            ldout[2 * gp + half] = v;
        }
    }
}

extern "C" void kernel_launch(void* const* d_in, const int* in_sizes, int n_in,
                              void* d_out, int out_size) {
    const float* x  = (const float*)d_in[0];
    const float* uw = (const float*)d_in[1];
    const float* uh = (const float*)d_in[2];
    const float* ud = (const float*)d_in[3];
    float* out = (float*)d_out;

    spline_kernel<<<GRIDB, 256>>>(x, uw, uh, ud, out, out + (size_t)BB * DD);
}

// round 8
// speedup vs baseline: 1.2105x; 1.0779x over previous
#include <cuda_runtime.h>

// ComponentWiseSpline: rational-quadratic spline flow, forward + log|det J|.
// B=65536 rows, D=128 dims, K=8 interior bins.
// R8: lane owns 2 adjacent dims, 2-warp team per row (1 reduction chain per
//     64 elems), 3-step butterfly + 4-lane partials, float2 I/O,
//     FSET+FADD search, identity-extended 10-bin table, guard-free loop,
//     launch_bounds(256,5), persistent grid 740 (=148x5).

#define BB 65536
#define DD 128
#define KK 8
#define NBINS 10                        // identity | 8 interior | identity
#define GRIDB 740                       // 148 SMs * 5 blocks
#define SPB 4                           // row streams per block (8 warps / 2)
#define NS (GRIDB * SPB)                // 2960 row streams
#define MAXR ((BB + NS - 1) / NS)       // 23

__device__ __forceinline__ float fsetge(float a, float b) {
    float r;
    asm("set.ge.f32.f32 %0, %1, %2;" : "=f"(r) : "f"(a), "f"(b));
    return r;
}

__global__ void __launch_bounds__(256, 5)
spline_kernel(const float* __restrict__ x,
              const float* __restrict__ uw,
              const float* __restrict__ uh,
              const float* __restrict__ ud,
              float* __restrict__ uout,
              float* __restrict__ ldout) {
    __shared__ float4 sTA[NBINS * DD];          // 20 KB {invW, -cw*invW, cumH, H}
    __shared__ float4 sTB[NBINS * DD];          // 20 KB {delta, d0, d1, e}
    __shared__ float  sThr[9 * DD];             // 4.5 KB
    __shared__ float  sPart[SPB][2][MAXR][4];   // 2.9 KB

    const int tid  = threadIdx.x;
    const int lane = tid & 31;
    const int warp = tid >> 5;          // 0..7
    const int strm = warp >> 1;         // 0..3  (stream within block)
    const int half = warp & 1;          // 0..1  (which 64-dim half of the row)

    // ---- per-block table build: thread dd (<128) builds dim dd ----
    if (tid < DD) {
        const float BOUND = 3.0f;
        const float MINW = 1e-3f, MINH = 1e-3f, MIND = 1e-3f, EPS = 1e-6f;
        const int dd = tid;

        float w[KK], h[KK];
        float m = -1e30f;
        #pragma unroll
        for (int k = 0; k < KK; k++) { w[k] = uw[dd * KK + k]; m = fmaxf(m, w[k]); }
        float s = 0.f;
        #pragma unroll
        for (int k = 0; k < KK; k++) { w[k] = expf(w[k] - m); s += w[k]; }
        float invs = 1.0f / s;
        #pragma unroll
        for (int k = 0; k < KK; k++) w[k] = MINW + (1.0f - MINW * KK) * (w[k] * invs);

        m = -1e30f;
        #pragma unroll
        for (int k = 0; k < KK; k++) { h[k] = uh[dd * KK + k]; m = fmaxf(m, h[k]); }
        s = 0.f;
        #pragma unroll
        for (int k = 0; k < KK; k++) { h[k] = expf(h[k] - m); s += h[k]; }
        invs = 1.0f / s;
        #pragma unroll
        for (int k = 0; k < KK; k++) h[k] = MINH + (1.0f - MINH * KK) * (h[k] * invs);

        float cw[KK + 1], ch[KK + 1];
        cw[0] = -BOUND; ch[0] = -BOUND;
        float accw = 0.f, acch = 0.f;
        #pragma unroll
        for (int k = 1; k < KK; k++) {
            accw += w[k - 1]; cw[k] = fmaf(2.0f * BOUND, accw, -BOUND);
            acch += h[k - 1]; ch[k] = fmaf(2.0f * BOUND, acch, -BOUND);
        }
        cw[KK] = BOUND; ch[KK] = BOUND;

        float dv[KK + 1];
        dv[0] = 1.0f - MIND; dv[KK] = 1.0f - MIND;
        #pragma unroll
        for (int k = 1; k < KK; k++) {
            float v = ud[dd * (KK - 1) + (k - 1)];
            dv[k] = MIND + fmaxf(v, 0.0f) + log1pf(expf(-fabsf(v)));
        }

        // smem slot remap: dim dd = h*64 + 2*pos + c  ->  slot h*64 + c*32 + pos
        const int hh  = dd >> 6;
        const int rem = dd & 63;
        const int s_slot = (hh << 6) + ((rem & 1) << 5) + (rem >> 1);

        #pragma unroll
        for (int k = 0; k < KK; k++) {
            float W = cw[k + 1] - cw[k];
            float H = ch[k + 1] - ch[k];
            float invW = 1.0f / W;
            float del  = H * invW;
            sTA[(k + 1) * DD + s_slot] = make_float4(invW, -cw[k] * invW, ch[k], H);
            sTB[(k + 1) * DD + s_slot] = make_float4(del, dv[k], dv[k + 1],
                                                     dv[k] + dv[k + 1] - 2.0f * del);
        }
        // identity bins 0 (x < -3) and 9 (x > 3): u = x, lad ~ 0
        const float4 idA = make_float4(1.0f, 0.0f, 0.0f, 1.0f);
        const float4 idB = make_float4(1.0f, 1.0f, 1.0f, 0.0f);
        sTA[0 * DD + s_slot] = idA; sTB[0 * DD + s_slot] = idB;
        sTA[9 * DD + s_slot] = idA; sTB[9 * DD + s_slot] = idB;

        sThr[0 * DD + s_slot] = -3.0f;
        #pragma unroll
        for (int t = 1; t < 8; t++) sThr[t * DD + s_slot] = cw[t] + EPS;
        sThr[8 * DD + s_slot] = __int_as_float(0x40400001);   // nextafter(3.0f)
    }
    __syncthreads();

    // ---- this lane's 2x9 thresholds into registers ----
    float thr[2][9];
    #pragma unroll
    for (int c = 0; c < 2; c++) {
        const int slot = (half << 6) + (c << 5) + lane;
        #pragma unroll
        for (int j = 0; j < 9; j++) thr[c][j] = sThr[j * DD + slot];
    }

    const int S = blockIdx.x * SPB + strm;          // stream id, 0..NS-1
    const int cnt = (BB - S + NS - 1) / NS;         // 22 or 23 rows
    const size_t STEP = (size_t)NS * DD;
    const int coloff = (half << 6) + (lane << 1);   // dim of c=0

    const float* px = x + (size_t)S * DD + coloff;
    float*       pu = uout + (size_t)S * DD + coloff;
    float2 xv = *reinterpret_cast<const float2*>(px);

    for (int ri = 0; ri < cnt; ri++) {
        float2 xnext;
        if (ri < cnt - 1)
            xnext = *reinterpret_cast<const float2*>(px + STEP);

        float uo[2], lad = 0.f;
        float xin[2] = {xv.x, xv.y};
        #pragma unroll
        for (int c = 0; c < 2; c++) {
            const float xs = xin[c];
            float s0 = fsetge(xs, thr[c][0]) + fsetge(xs, thr[c][1]);
            float s1 = fsetge(xs, thr[c][2]) + fsetge(xs, thr[c][3]);
            float s2 = fsetge(xs, thr[c][4]) + fsetge(xs, thr[c][5]);
            float s3 = fsetge(xs, thr[c][6]) + fsetge(xs, thr[c][7]);
            float kf = ((s0 + s1) + (s2 + s3)) + fsetge(xs, thr[c][8]);
            const int idx = __float2int_rz(kf) * DD + (half << 6) + (c << 5) + lane;

            const float4 A  = sTA[idx];     // invW, -cw*invW, cumH, H
            const float4 Bv = sTB[idx];     // delta, d0, d1, e

            const float theta = fmaf(xs, A.x, A.y);
            const float omt   = 1.0f - theta;
            const float th2   = theta * theta;
            const float t1m   = theta * omt;
            const float omt2  = omt * omt;
            const float t1m2  = t1m + t1m;

            const float num    = A.w * fmaf(Bv.x, th2, Bv.y * t1m);
            const float den    = fmaf(Bv.w, t1m, Bv.x);
            const float invden = __fdividef(1.0f, den);
            uo[c] = fmaf(num, invden, A.z);

            const float inner = fmaf(Bv.z, th2, fmaf(Bv.x, t1m2, Bv.y * omt2));
            const float dnum  = (Bv.x * Bv.x) * inner;
            lad += __logf(dnum * (invden * invden));
        }

        *reinterpret_cast<float2*>(pu) = make_float2(uo[0], uo[1]);

        // 3-step butterfly: lanes 0..3 end with the 4 group sums
        lad += __shfl_xor_sync(0xffffffffu, lad, 16);
        lad += __shfl_xor_sync(0xffffffffu, lad, 8);
        lad += __shfl_xor_sync(0xffffffffu, lad, 4);
        if (lane < 4) sPart[strm][half][ri][lane] = lad;

        px += STEP;
        pu += STEP;
        xv = xnext;
    }
    __syncthreads();

    // ---- combine 8 partials per row, write log|det J| ----
    if (tid < SPB * MAXR) {
        const int st = tid / MAXR;
        const int ri = tid - st * MAXR;
        const int r  = blockIdx.x * SPB + st + ri * NS;
        if (r < BB) {
            const float* p0 = sPart[st][0][ri];
            const float* p1 = sPart[st][1][ri];
            ldout[r] = ((p0[0] + p0[1]) + (p0[2] + p0[3])) +
                       ((p1[0] + p1[1]) + (p1[2] + p1[3]));
        }
    }
}

extern "C" void kernel_launch(void* const* d_in, const int* in_sizes, int n_in,
                              void* d_out, int out_size) {
    const float* x  = (const float*)d_in[0];
    const float* uw = (const float*)d_in[1];
    const float* uh = (const float*)d_in[2];
    const float* ud = (const float*)d_in[3];
    float* out = (float*)d_out;

    spline_kernel<<<GRIDB, 256>>>(x, uw, uh, ud, out, out + (size_t)BB * DD);
}

// round 10
// speedup vs baseline: 1.3034x; 1.0767x over previous
#include <cuda_runtime.h>

// ComponentWiseSpline: rational-quadratic spline flow, forward + log|det J|.
// B=65536 rows, D=128 dims, K=8 interior bins.
// R10: R4's exact instruction stream (FSET+FADD search, identity-extended
//      10-bin table, 4-warp team per row-pair, depth-1 prefetch) at higher
//      occupancy: 512-thread blocks, launch_bounds(512,3), grid 444=148x3.

#define BB 65536
#define DD 128
#define KK 8
#define NBINS 10                         // identity | 8 interior | identity
#define NPAIRS (BB / 2)                  // 32768 row-pairs
#define BLOCK 512
#define TEAMS 4                          // 4-warp teams per block
#define GRIDB 444                        // 148 SMs * 3 blocks
#define NSP (GRIDB * TEAMS)              // 1776 row-pair streams
#define MAXP ((NPAIRS + NSP - 1) / NSP)  // 19

__device__ __forceinline__ float fsetge(float a, float b) {
    float r;
    asm("set.ge.f32.f32 %0, %1, %2;" : "=f"(r) : "f"(a), "f"(b));
    return r;
}

__global__ void __launch_bounds__(BLOCK, 3)
spline_kernel(const float* __restrict__ x,
              const float* __restrict__ uw,
              const float* __restrict__ uh,
              const float* __restrict__ ud,
              float* __restrict__ uout,
              float* __restrict__ ldout) {
    __shared__ float4 sTA[NBINS * DD];            // 20 KB {invW, -cw*invW, cumH, H}
    __shared__ float4 sTB[NBINS * DD];            // 20 KB {delta, d0, d1, e}
    __shared__ float  sThr[9 * DD];               // 4.5 KB
    __shared__ float  sPart[TEAMS][4][MAXP][2];   // 2.4 KB

    const int tid  = threadIdx.x;
    const int lane = tid & 31;
    const int warp = tid >> 5;       // 0..15
    const int team = warp >> 2;      // 0..3
    const int wslot = warp & 3;      // 0..3
    const int d = (wslot << 5) + lane;

    // ---- per-block table build: thread dd (<128) builds dim dd ----
    if (tid < DD) {
        const float BOUND = 3.0f;
        const float MINW = 1e-3f, MINH = 1e-3f, MIND = 1e-3f, EPS = 1e-6f;
        const int dd = tid;

        float w[KK], h[KK];
        float m = -1e30f;
        #pragma unroll
        for (int k = 0; k < KK; k++) { w[k] = uw[dd * KK + k]; m = fmaxf(m, w[k]); }
        float s = 0.f;
        #pragma unroll
        for (int k = 0; k < KK; k++) { w[k] = expf(w[k] - m); s += w[k]; }
        float invs = 1.0f / s;
        #pragma unroll
        for (int k = 0; k < KK; k++) w[k] = MINW + (1.0f - MINW * KK) * (w[k] * invs);

        m = -1e30f;
        #pragma unroll
        for (int k = 0; k < KK; k++) { h[k] = uh[dd * KK + k]; m = fmaxf(m, h[k]); }
        s = 0.f;
        #pragma unroll
        for (int k = 0; k < KK; k++) { h[k] = expf(h[k] - m); s += h[k]; }
        invs = 1.0f / s;
        #pragma unroll
        for (int k = 0; k < KK; k++) h[k] = MINH + (1.0f - MINH * KK) * (h[k] * invs);

        float cw[KK + 1], ch[KK + 1];
        cw[0] = -BOUND; ch[0] = -BOUND;
        float accw = 0.f, acch = 0.f;
        #pragma unroll
        for (int k = 1; k < KK; k++) {
            accw += w[k - 1]; cw[k] = fmaf(2.0f * BOUND, accw, -BOUND);
            acch += h[k - 1]; ch[k] = fmaf(2.0f * BOUND, acch, -BOUND);
        }
        cw[KK] = BOUND; ch[KK] = BOUND;

        float dv[KK + 1];
        dv[0] = 1.0f - MIND; dv[KK] = 1.0f - MIND;
        #pragma unroll
        for (int k = 1; k < KK; k++) {
            float v = ud[dd * (KK - 1) + (k - 1)];
            dv[k] = MIND + fmaxf(v, 0.0f) + log1pf(expf(-fabsf(v)));
        }

        #pragma unroll
        for (int k = 0; k < KK; k++) {
            float W = cw[k + 1] - cw[k];
            float H = ch[k + 1] - ch[k];
            float invW = 1.0f / W;
            float del  = H * invW;
            sTA[(k + 1) * DD + dd] = make_float4(invW, -cw[k] * invW, ch[k], H);
            sTB[(k + 1) * DD + dd] = make_float4(del, dv[k], dv[k + 1],
                                                 dv[k] + dv[k + 1] - 2.0f * del);
        }
        // identity bins 0 (x < -3) and 9 (x > 3): u = x, lad = 0 (to fp rounding)
        const float4 idA = make_float4(1.0f, 0.0f, 0.0f, 1.0f);
        const float4 idB = make_float4(1.0f, 1.0f, 1.0f, 0.0f);
        sTA[0 * DD + dd] = idA; sTB[0 * DD + dd] = idB;
        sTA[9 * DD + dd] = idA; sTB[9 * DD + dd] = idB;

        sThr[0 * DD + dd] = -3.0f;
        #pragma unroll
        for (int t = 1; t < 8; t++) sThr[t * DD + dd] = cw[t] + EPS;
        sThr[8 * DD + dd] = __int_as_float(0x40400001);   // nextafter(3.0f)
    }
    __syncthreads();

    // ---- this lane's 9 thresholds into registers ----
    float thr[9];
    #pragma unroll
    for (int j = 0; j < 9; j++) thr[j] = sThr[j * DD + d];

    const int S = blockIdx.x * TEAMS + team;        // stream id, 0..NSP-1
    const int cnt = (NPAIRS - S + NSP - 1) / NSP;   // 18 or 19 pairs
    const size_t STEP = (size_t)NSP * 256;

    const float* px = x + (size_t)S * 256 + d;
    float*       pu = uout + (size_t)S * 256 + d;
    float xa = px[0];
    float xb = px[DD];

    for (int pi = 0; pi < cnt; pi++) {
        float xa2, xb2;
        if (pi < cnt - 1) {
            xa2 = __ldg(px + STEP);
            xb2 = __ldg(px + STEP + DD);
        }

        float lads[2];
        float xin[2] = {xa, xb};
        #pragma unroll
        for (int e = 0; e < 2; e++) {
            const float xv = xin[e];
            float s0 = fsetge(xv, thr[0]) + fsetge(xv, thr[1]);
            float s1 = fsetge(xv, thr[2]) + fsetge(xv, thr[3]);
            float s2 = fsetge(xv, thr[4]) + fsetge(xv, thr[5]);
            float s3 = fsetge(xv, thr[6]) + fsetge(xv, thr[7]);
            float kf = ((s0 + s1) + (s2 + s3)) + fsetge(xv, thr[8]);
            const int idx = __float2int_rz(kf) * DD + d;

            const float4 A  = sTA[idx];   // invW, -cw*invW, cumH, H
            const float4 Bv = sTB[idx];   // delta, d0, d1, e

            const float theta = fmaf(xv, A.x, A.y);
            const float omt   = 1.0f - theta;
            const float th2   = theta * theta;
            const float t1m   = theta * omt;
            const float omt2  = omt * omt;
            const float t1m2  = t1m + t1m;

            const float num    = A.w * fmaf(Bv.x, th2, Bv.y * t1m);
            const float den    = fmaf(Bv.w, t1m, Bv.x);
            const float invden = __fdividef(1.0f, den);
            const float uo     = fmaf(num, invden, A.z);

            const float inner = fmaf(Bv.z, th2, fmaf(Bv.x, t1m2, Bv.y * omt2));
            const float dnum  = (Bv.x * Bv.x) * inner;
            lads[e] = __logf(dnum * (invden * invden));

            pu[e ? DD : 0] = uo;
        }

        float la = lads[0], lb = lads[1];
        #pragma unroll
        for (int off = 16; off; off >>= 1) {
            la += __shfl_xor_sync(0xffffffffu, la, off);
            lb += __shfl_xor_sync(0xffffffffu, lb, off);
        }
        if (lane == 0) {
            sPart[team][wslot][pi][0] = la;
            sPart[team][wslot][pi][1] = lb;
        }

        px += STEP;
        pu += STEP;
        xa = xa2;
        xb = xb2;
    }
    __syncthreads();

    // ---- combine 4 warp-partials per row, write log|det J| ----
    if (tid < TEAMS * MAXP * 2) {
        const int tm   = tid / (MAXP * 2);
        const int rem  = tid - tm * (MAXP * 2);
        const int ppi  = rem >> 1;
        const int half = rem & 1;
        const int gp   = blockIdx.x * TEAMS + tm + ppi * NSP;
        if (gp < NPAIRS) {
            float v = sPart[tm][0][ppi][half] + sPart[tm][1][ppi][half]
                    + sPart[tm][2][ppi][half] + sPart[tm][3][ppi][half];
            ldout[2 * gp + half] = v;
        }
    }
}

extern "C" void kernel_launch(void* const* d_in, const int* in_sizes, int n_in,
                              void* d_out, int out_size) {
    const float* x  = (const float*)d_in[0];
    const float* uw = (const float*)d_in[1];
    const float* uh = (const float*)d_in[2];
    const float* ud = (const float*)d_in[3];
    float* out = (float*)d_out;

    spline_kernel<<<GRIDB, BLOCK>>>(x, uw, uh, ud, out, out + (size_t)BB * DD);
}